// round 10
// baseline (speedup 1.0000x reference)
#include <cuda_runtime.h>
#include <cstdint>

#define NNODES 100000
#define NEDGES 1600000
#define IN_C 64
#define HID 128
#define OUT_C 64
#define NBT 128            // nodes per MLP tile
#define NTILES ((NNODES + NBT - 1) / NBT)   // 782
#define XT_STR 132
#define HT_STR 132
#define MLP_THREADS 512
#define SCAN_BLK 1024
#define SCAN_NB ((NNODES + SCAN_BLK - 1) / SCAN_BLK)   // 98 blocks, co-resident

typedef unsigned long long ull;

// Scratch (static device arrays; heap alloc is forbidden)
__device__ __align__(16) float g_h2[(size_t)NNODES * OUT_C]; // unscaled h2, 25.6 MB
__device__ float g_dinv[NNODES];
__device__ int   g_degi[NNODES];
__device__ int   g_off[NNODES];      // CSR offsets; scatter bumps them to 'end'
__device__ int   g_esrc[NEDGES];
__device__ unsigned long long g_scanstate[SCAN_NB];

// ---- f32x2 packed helpers (Blackwell) ----
__device__ __forceinline__ ull dup2(float v) {
    ull r; asm("mov.b64 %0, {%1, %1};" : "=l"(r) : "f"(v)); return r;
}
__device__ __forceinline__ void unpack2(ull p, float& lo, float& hi) {
    asm("mov.b64 {%0, %1}, %2;" : "=f"(lo), "=f"(hi) : "l"(p));
}
__device__ __forceinline__ void ffma2(ull& d, ull a, ull b) {
    asm("fma.rn.f32x2 %0, %1, %2, %0;" : "+l"(d) : "l"(a), "l"(b));
}

// ---------------------------------------------------------------------------
__device__ __forceinline__ int detect_stride(const int* __restrict__ ei, int* s_st) {
    if (threadIdx.x < 32) {
        int z = (ei[2 * threadIdx.x + 1] == 0);
        unsigned m = __ballot_sync(0xFFFFFFFFu, z);
        if (threadIdx.x == 0) *s_st = (m == 0xFFFFFFFFu) ? 2 : 1;
    }
    __syncthreads();
    return *s_st;
}

__global__ __launch_bounds__(256) void k_deg_count(const int* __restrict__ ei) {
    __shared__ int s_st;
    const int st = detect_stride(ei, &s_st);
    int e = blockIdx.x * blockDim.x + threadIdx.x;
    if (e < NEDGES) {
        int d = ei[(size_t)NEDGES * st + (size_t)e * st];
        if ((unsigned)d < NNODES) atomicAdd(&g_degi[d], 1);
    }
}

// ---------------------------------------------------------------------------
// Single-pass exclusive scan (decoupled lookback) of g_degi -> g_off; + dinv.
// ---------------------------------------------------------------------------
__global__ __launch_bounds__(SCAN_BLK) void k_scan() {
    __shared__ int wsum[32];
    __shared__ int s_total, s_prefix;
    const int t = threadIdx.x;
    const int bid = blockIdx.x;
    const int i = bid * SCAN_BLK + t;
    const int v = (i < NNODES) ? g_degi[i] : 0;
    if (i < NNODES) g_dinv[i] = rsqrtf((float)(v + 1));

    int x = v;
    #pragma unroll
    for (int o = 1; o < 32; o <<= 1) {
        int y = __shfl_up_sync(0xFFFFFFFFu, x, o);
        if ((t & 31) >= o) x += y;
    }
    if ((t & 31) == 31) wsum[t >> 5] = x;
    __syncthreads();
    if (t < 32) {
        int w = wsum[t];
        int xx = w;
        #pragma unroll
        for (int o = 1; o < 32; o <<= 1) {
            int y = __shfl_up_sync(0xFFFFFFFFu, xx, o);
            if (t >= o) xx += y;
        }
        wsum[t] = xx - w;
        if (t == 31) s_total = xx;
    }
    __syncthreads();

    if (t == 0) {
        unsigned long long flag = (bid == 0) ? 2ULL : 1ULL;
        __threadfence();
        *(volatile unsigned long long*)&g_scanstate[bid] =
            (flag << 32) | (unsigned)s_total;
        if (bid == 0) s_prefix = 0;
    }

    if (bid > 0 && t < 32) {
        int running = 0;
        int base = bid - 1;
        for (;;) {
            int j = base - t;
            unsigned long long s;
            if (j >= 0) {
                do { s = *(volatile unsigned long long*)&g_scanstate[j]; }
                while ((s >> 32) == 0);
            } else {
                s = (2ULL << 32);
            }
            int flag = (int)(s >> 32);
            int val  = (int)(s & 0xFFFFFFFFu);
            unsigned pmask = __ballot_sync(0xFFFFFFFFu, flag == 2);
            if (pmask) {
                int stop = __ffs(pmask) - 1;
                int contrib = (t <= stop) ? val : 0;
                #pragma unroll
                for (int o = 16; o >= 1; o >>= 1)
                    contrib += __shfl_down_sync(0xFFFFFFFFu, contrib, o);
                running += __shfl_sync(0xFFFFFFFFu, contrib, 0);
                break;
            } else {
                int contrib = val;
                #pragma unroll
                for (int o = 16; o >= 1; o >>= 1)
                    contrib += __shfl_down_sync(0xFFFFFFFFu, contrib, o);
                running += __shfl_sync(0xFFFFFFFFu, contrib, 0);
                base -= 32;
            }
        }
        if (t == 0) {
            __threadfence();
            *(volatile unsigned long long*)&g_scanstate[bid] =
                (2ULL << 32) | (unsigned)(running + s_total);
            s_prefix = running;
        }
    }
    __syncthreads();

    if (i < NNODES) g_off[i] = (x - v + wsum[t >> 5]) + s_prefix;
}

__global__ __launch_bounds__(256) void k_scatter(const int* __restrict__ ei) {
    __shared__ int s_st;
    const int st = detect_stride(ei, &s_st);
    int e = blockIdx.x * blockDim.x + threadIdx.x;
    if (e < NEDGES) {
        int s = ei[(size_t)e * st];
        int d = ei[(size_t)NEDGES * st + (size_t)e * st];
        if ((unsigned)s < NNODES && (unsigned)d < NNODES) {
            int pos = atomicAdd(&g_off[d], 1);
            g_esrc[pos] = s;
        }
    }
}

// ---------------------------------------------------------------------------
// relu + store 8 node-values (4 packed pairs) of one sHT row
// ---------------------------------------------------------------------------
__device__ __forceinline__ void relu_store8(float* dst, const ull* p) {
    float l0,h0,l1,h1,l2,h2,l3,h3;
    unpack2(p[0], l0, h0); unpack2(p[1], l1, h1);
    unpack2(p[2], l2, h2); unpack2(p[3], l3, h3);
    *(float4*)dst       = make_float4(fmaxf(l0,0.f), fmaxf(h0,0.f), fmaxf(l1,0.f), fmaxf(h1,0.f));
    *(float4*)(dst + 4) = make_float4(fmaxf(l2,0.f), fmaxf(h2,0.f), fmaxf(l3,0.f), fmaxf(h3,0.f));
}

// ---------------------------------------------------------------------------
// Fused MLP with packed f32x2 FMA (FFMA2): halves FMA-pipe instruction count.
//   g_h2[n] = relu(X@W1+b1)[n] @ W2
// sHT rows stored under phi(col) = (col&3)*32 + (col>>2); sW2s pre-permuted.
// All accumulator indices compile-time.
// ---------------------------------------------------------------------------
__global__ __launch_bounds__(MLP_THREADS, 1) void k_mlp(
    const float* __restrict__ X, const float* __restrict__ W1,
    const float* __restrict__ b1, const float* __restrict__ W2)
{
    extern __shared__ float sm[];
    float* sW1  = sm;                    // 64*128 [k][col]
    float* sW2s = sW1 + IN_C * HID;      // 128*64 [phi(k)][col]
    float* sb1  = sW2s + HID * OUT_C;    // 128
    float* sXT  = sb1 + HID;             // 64 x XT_STR  [k][node]
    float* sHT  = sXT + IN_C * XT_STR;   // 128 x HT_STR [phi(col)][node]

    const int t = threadIdx.x;

    for (int i = t; i < IN_C * HID / 4; i += MLP_THREADS)
        ((float4*)sW1)[i] = ((const float4*)W1)[i];
    for (int i = t; i < HID * OUT_C / 4; i += MLP_THREADS) {
        int k = i >> 4, cq = i & 15;
        int r = (k & 3) * 32 + (k >> 2);          // phi(k)
        ((float4*)sW2s)[r * 16 + cq] = ((const float4*)W2)[i];
    }
    if (t < HID) sb1[t] = b1[t];

    const int c4a = t & 31;            // phase1: col quad (32 x 4 = 128 cols)
    const int no  = t >> 5;            // phase1: node octet — warp-uniform
    const int c2  = t & 31;            // phase2: col pair (32 x 2 = 64 cols)
    const int n8  = t >> 5;            // phase2: node octet — warp-uniform
    const int sn  = t & 127;           // staging: node
    const int skq = t >> 7;            // staging: k quarter (0..3)

    for (int tile = blockIdx.x; tile < NTILES; tile += gridDim.x) {
        const int base = tile * NBT;

        // ---- stage X^T [k][node]: 16 k-values of one node per thread ----
        {
            const int gn = base + sn;
            if (gn < NNODES) {
                const float4* xr = (const float4*)(X + (size_t)gn * IN_C + skq * 16);
                #pragma unroll
                for (int f = 0; f < 4; f++) {
                    float4 v = xr[f];
                    int k = skq * 16 + f * 4;
                    sXT[(k + 0) * XT_STR + sn] = v.x;
                    sXT[(k + 1) * XT_STR + sn] = v.y;
                    sXT[(k + 2) * XT_STR + sn] = v.z;
                    sXT[(k + 3) * XT_STR + sn] = v.w;
                }
            } else {
                #pragma unroll
                for (int f = 0; f < 4; f++) {
                    int k = skq * 16 + f * 4;
                    sXT[(k + 0) * XT_STR + sn] = 0.f;
                    sXT[(k + 1) * XT_STR + sn] = 0.f;
                    sXT[(k + 2) * XT_STR + sn] = 0.f;
                    sXT[(k + 3) * XT_STR + sn] = 0.f;
                }
            }
        }
        __syncthreads();

        // ---- Phase 1: 4 cols x 8 nodes per thread, packed node-pairs ----
        {
            float4 bias = ((const float4*)sb1)[c4a];
            ull bd0 = dup2(bias.x), bd1 = dup2(bias.y);
            ull bd2 = dup2(bias.z), bd3 = dup2(bias.w);
            ull p0[4], p1[4], p2[4], p3[4];
            #pragma unroll
            for (int j = 0; j < 4; j++) { p0[j]=bd0; p1[j]=bd1; p2[j]=bd2; p3[j]=bd3; }

            #pragma unroll 8
            for (int k = 0; k < IN_C; k++) {
                float4 w = *(const float4*)&sW1[k * HID + c4a * 4];
                ull a0 = dup2(w.x), a1 = dup2(w.y), a2 = dup2(w.z), a3 = dup2(w.w);
                const ull* xp = (const ull*)&sXT[k * XT_STR + no * 8];
                ull b0 = xp[0], b1 = xp[1], b2 = xp[2], b3 = xp[3];
                ffma2(p0[0],a0,b0); ffma2(p0[1],a0,b1); ffma2(p0[2],a0,b2); ffma2(p0[3],a0,b3);
                ffma2(p1[0],a1,b0); ffma2(p1[1],a1,b1); ffma2(p1[2],a1,b2); ffma2(p1[3],a1,b3);
                ffma2(p2[0],a2,b0); ffma2(p2[1],a2,b1); ffma2(p2[2],a2,b2); ffma2(p2[3],a2,b3);
                ffma2(p3[0],a3,b0); ffma2(p3[1],a3,b1); ffma2(p3[2],a3,b2); ffma2(p3[3],a3,b3);
            }

            // relu + store rows phi(col) = c*32 + c4a (compile-time c)
            relu_store8(&sHT[(0 * 32 + c4a) * HT_STR + no * 8], p0);
            relu_store8(&sHT[(1 * 32 + c4a) * HT_STR + no * 8], p1);
            relu_store8(&sHT[(2 * 32 + c4a) * HT_STR + no * 8], p2);
            relu_store8(&sHT[(3 * 32 + c4a) * HT_STR + no * 8], p3);
        }
        __syncthreads();

        // ---- Phase 2: 2 cols x 8 nodes per thread, packed node-pairs ----
        {
            ull q0[4], q1[4];
            #pragma unroll
            for (int j = 0; j < 4; j++) { q0[j] = 0ULL; q1[j] = 0ULL; }

            #pragma unroll 8
            for (int r = 0; r < HID; r++) {
                float2 w = *(const float2*)&sW2s[r * OUT_C + c2 * 2];
                ull a0 = dup2(w.x), a1 = dup2(w.y);
                const ull* xp = (const ull*)&sHT[r * HT_STR + n8 * 8];
                ull b0 = xp[0], b1 = xp[1], b2 = xp[2], b3 = xp[3];
                ffma2(q0[0],a0,b0); ffma2(q0[1],a0,b1); ffma2(q0[2],a0,b2); ffma2(q0[3],a0,b3);
                ffma2(q1[0],a1,b0); ffma2(q1[1],a1,b1); ffma2(q1[2],a1,b2); ffma2(q1[3],a1,b3);
            }

            #pragma unroll
            for (int j = 0; j < 4; j++) {
                float l0,h0,l1,h1;
                unpack2(q0[j], l0, h0);
                unpack2(q1[j], l1, h1);
                int gn0 = base + n8 * 8 + 2 * j;
                int gn1 = gn0 + 1;
                if (gn0 < NNODES)
                    *(float2*)&g_h2[(size_t)gn0 * OUT_C + c2 * 2] = make_float2(l0, l1);
                if (gn1 < NNODES)
                    *(float2*)&g_h2[(size_t)gn1 * OUT_C + c2 * 2] = make_float2(h0, h1);
            }
        }
        __syncthreads();
    }
}

// ---------------------------------------------------------------------------
// Pull aggregation: one warp per dst node, lane owns a float2 column chunk.
// ---------------------------------------------------------------------------
__global__ __launch_bounds__(256) void k_pull(
    const float* __restrict__ b2, float* __restrict__ out)
{
    const int warp = (blockIdx.x * blockDim.x + threadIdx.x) >> 5;
    const int lane = threadIdx.x & 31;
    if (warp >= NNODES) return;
    const int n = warp;

    const float2* __restrict__ tab = (const float2*)g_h2;
    const float din = g_dinv[n];

    float2 self = tab[(size_t)n * (OUT_C / 2) + lane];
    float2 acc;
    acc.x = din * self.x;
    acc.y = din * self.y;

    const int deg = g_degi[n];
    const int end = g_off[n];
    const int beg = end - deg;

    int i = beg;
    for (; i + 1 < end; i += 2) {
        const int s0 = __ldg(&g_esrc[i]);
        const int s1 = __ldg(&g_esrc[i + 1]);
        const float d0 = g_dinv[s0];
        const float d1 = g_dinv[s1];
        float2 v0 = tab[(size_t)s0 * (OUT_C / 2) + lane];
        float2 v1 = tab[(size_t)s1 * (OUT_C / 2) + lane];
        acc.x = fmaf(d0, v0.x, acc.x);
        acc.y = fmaf(d0, v0.y, acc.y);
        acc.x = fmaf(d1, v1.x, acc.x);
        acc.y = fmaf(d1, v1.y, acc.y);
    }
    if (i < end) {
        const int s = __ldg(&g_esrc[i]);
        const float ds = g_dinv[s];
        float2 v = tab[(size_t)s * (OUT_C / 2) + lane];
        acc.x = fmaf(ds, v.x, acc.x);
        acc.y = fmaf(ds, v.y, acc.y);
    }

    const float2 bb = ((const float2*)b2)[lane];
    float2 o;
    o.x = fmaf(din, acc.x, bb.x);
    o.y = fmaf(din, acc.y, bb.y);
    ((float2*)out)[(size_t)n * (OUT_C / 2) + lane] = o;
}

// ---------------------------------------------------------------------------
extern "C" void kernel_launch(void* const* d_in, const int* in_sizes, int n_in,
                              void* d_out, int out_size)
{
    const float* X   = (const float*)d_in[0];
    const int*   ei  = (const int*)d_in[1];
    const float* W1  = (const float*)d_in[2];
    const float* b1  = (const float*)d_in[3];
    const float* W2  = (const float*)d_in[4];
    const float* b2  = (const float*)d_in[5];
    float*       out = (float*)d_out;

    const int smem_bytes =
        (IN_C*HID + HID*OUT_C + HID + IN_C*XT_STR + HID*HT_STR) * 4;  // ~164 KB

    static cudaStream_t s1;
    static cudaEvent_t evRoot, evMlp;
    static void *p_degi, *p_state;
    static int init_done = 0;
    if (!init_done) {
        cudaFuncSetAttribute(k_mlp, cudaFuncAttributeMaxDynamicSharedMemorySize, smem_bytes);
        cudaStreamCreateWithFlags(&s1, cudaStreamNonBlocking);
        cudaEventCreateWithFlags(&evRoot, cudaEventDisableTiming);
        cudaEventCreateWithFlags(&evMlp, cudaEventDisableTiming);
        cudaGetSymbolAddress(&p_degi, g_degi);
        cudaGetSymbolAddress(&p_state, g_scanstate);
        init_done = 1;
    }

    cudaEventRecord(evRoot, 0);

    // Critical chain on the capture (legacy) stream.
    cudaMemsetAsync(p_degi, 0, NNODES * sizeof(int), 0);
    cudaMemsetAsync(p_state, 0, SCAN_NB * sizeof(unsigned long long), 0);
    k_deg_count<<<(NEDGES + 255) / 256, 256>>>(ei);
    k_scan     <<<SCAN_NB, SCAN_BLK>>>();
    k_scatter  <<<(NEDGES + 255) / 256, 256>>>(ei);

    // Fork: MLP depends only on the root.
    cudaStreamWaitEvent(s1, evRoot, 0);
    k_mlp<<<148, MLP_THREADS, smem_bytes, s1>>>(X, W1, b1, W2);
    cudaEventRecord(evMlp, s1);

    // Join, then pull.
    cudaStreamWaitEvent(0, evMlp, 0);
    k_pull     <<<(NNODES * 32 + 255) / 256, 256>>>(b2, out);
}